// round 15
// baseline (speedup 1.0000x reference)
#include <cuda_runtime.h>

// CountVectorizer == per-row bincount over vocab followed by counts @ W + b.
//   out[b, :] = bias + sum_t W[token_ids[b, t], :]   (embedding gather-sum)
//
// Final ledger (same total gather bytes, one resident wave):
//   float4 unroll5 (R1):   12.4   | float2 unroll10 (R10): 12.29
//   float2 unroll5 (R6):   11.33  | float2 unroll2  (R12): 12.29
//   float1 (R8/9):         14.37  | pre-scaled offs (R13): 12.29
//   R6 + .cg (R11):        11.296 <- champion (this file, verbatim)
// Every axis swept and regresses in both directions around this point:
// width (float4/1), unroll (2/10), tokens-per-warp (forced by one-wave
// budget), work quantum (quarter-row), cache-op (.nc), L2 evict policy,
// occupancy caps, offset pre-scaling (R13: breaks the IMAD.WIDE fold on
// the LDS->LDG path). Delivery = 105 MB / 11.3 us ~ 9.3 TB/s ~ LTS cap.
// This round: R11 resubmitted byte-for-byte as the reproducibility check
// (rigor.md); R14's attempt died on a broker infra flake (4th occurrence),
// not the kernel - this exact source passed at 11.296 us in R11.

#define CV_BATCH  1024
#define CV_SEQ    200
#define CV_D      128               // d_model
#define CV_D2     (CV_D / 2)        // 64 float2 per full row
#define CV_HALF2  32                // float2 per half row (256 B)
#define CV_WARPS  4

__global__ __launch_bounds__(128)
void count_vectorizer_kernel(const int* __restrict__ token_ids,
                             const float2* __restrict__ W2,
                             const float2* __restrict__ bias2,
                             float2* __restrict__ out2)
{
    __shared__ int    s_ids[CV_SEQ];
    __shared__ float2 s_acc[CV_WARPS][CV_HALF2];

    const int b = blockIdx.x >> 1;        // batch row
    const int h = blockIdx.x & 1;         // d-half (0: floats 0..63, 1: 64..127)

    // Stage this row's 200 token ids (2 coalesced rounds of 128).
    for (int i = threadIdx.x; i < CV_SEQ; i += 128)
        s_ids[i] = token_ids[b * CV_SEQ + i];
    __syncthreads();

    const int lane = threadIdx.x & 31;    // float2 slice within the half-row
    const int w    = threadIdx.x >> 5;    // warp id 0..3 (token stream)
    const int dcol = h * CV_HALF2 + lane; // float2 column in the full row

    float2 acc = make_float2(0.f, 0.f);

    // 50 gathers per warp; unroll 5 = measured optimum (~5 LDG.64 in
    // flight: covers warm-L2 latency without deepening cross-CTA L1tex
    // queue contention). .cg: no L1 allocation (zero L1 reuse on a random
    // 51 MB table). Raw id here: ptxas folds id*64+dcol into IMAD.WIDE
    // addressing off the LDS result (pre-scaling regressed, R13).
    #pragma unroll 5
    for (int t = w; t < CV_SEQ; t += CV_WARPS) {
        const float2 v = __ldcg(&W2[s_ids[t] * CV_D2 + dcol]);
        acc.x += v.x; acc.y += v.y;
    }

    s_acc[w][lane] = acc;
    __syncthreads();

    // Warp 0 folds the 4 partials, adds bias, stores the 256B half-row.
    if (w == 0) {
        float2 a = s_acc[0][lane];
        #pragma unroll
        for (int g = 1; g < CV_WARPS; g++) {
            const float2 v = s_acc[g][lane];
            a.x += v.x; a.y += v.y;
        }
        const float2 bb = __ldg(&bias2[dcol]);
        a.x += bb.x; a.y += bb.y;
        out2[b * CV_D2 + dcol] = a;
    }
}

extern "C" void kernel_launch(void* const* d_in, const int* in_sizes, int n_in,
                              void* d_out, int out_size)
{
    const int*   token_ids = (const int*)d_in[0];      // [1024, 200] int32
    const float* W         = (const float*)d_in[1];    // [100000, 128] f32
    const float* bias      = (const float*)d_in[2];    // [128] f32
    float*       out       = (float*)d_out;            // [1024, 128] f32

    (void)in_sizes; (void)n_in; (void)out_size;

    count_vectorizer_kernel<<<2 * CV_BATCH, 128>>>(
        token_ids,
        reinterpret_cast<const float2*>(W),
        reinterpret_cast<const float2*>(bias),
        reinterpret_cast<float2*>(out));
}